// round 1
// baseline (speedup 1.0000x reference)
#include <cuda_runtime.h>
#include <math.h>

// ROC-Star pairwise loss, B=256, E=8192, C=19 (shapes derived at runtime).
//
// Structure per class c:
//   m2 = sum over (batch pos i, selected epoch neg j) relu(e_j + g - y_i)^2
//   m3 = sum over (selected epoch pos j, batch neg i) relu(y_i - e_j + g)^2
//   res = (m2 + m3)/1000 ; nan->0 ; degenerate -> sum(y_pred[:,c])*1e-8
// output = mean over classes.
//
// Strategy: compact selected epoch elements per 256-wide chunk (two-sided,
// deterministic ballot-based compaction), then each thread owns batch index
// tid (value in register, masked-out entries = 1e30 so relu kills them) and
// loops over the compacted t-values (shared-memory broadcast).

#define TPB 256
#define MAXC 32
#define MAXCH 64

__device__ float d_Apos[MAXC * TPB];   // y_i if batch-pos else 1e30
__device__ float d_Aneg[MAXC * TPB];   // -y_i if batch-neg else 1e30
__device__ int   d_npos[MAXC];
__device__ float d_sumyp[MAXC];
__device__ int   d_cap[MAXC];
__device__ float d_part[MAXC * MAXCH];

__global__ void setup_kernel(const float* __restrict__ y_pred,
                             const float* __restrict__ y_true,
                             const float* __restrict__ epoch_true,
                             int Bn, int Cn, int En)
{
    int c = blockIdx.x;
    int tid = threadIdx.x;
    bool valid = tid < Bn;
    float y = 0.f;
    bool pos = false;
    if (valid) {
        y = y_pred[tid * Cn + c];
        pos = y_true[tid * Cn + c] >= 0.5f;
    }
    d_Apos[c * TPB + tid] = (valid && pos)  ?  y : 1e30f;
    d_Aneg[c * TPB + tid] = (valid && !pos) ? -y : 1e30f;

    // cap_pos = count(epoch_true[:,c] >= 0.5)
    int capc = 0;
    for (int j = tid; j < En; j += TPB)
        capc += (epoch_true[j * Cn + c] >= 0.5f) ? 1 : 0;

    __shared__ float sf[TPB];
    __shared__ int   si[TPB];
    __shared__ int   sc[TPB];
    sf[tid] = valid ? y : 0.f;
    si[tid] = (valid && pos) ? 1 : 0;
    sc[tid] = capc;
    __syncthreads();
    for (int s = TPB / 2; s > 0; s >>= 1) {
        if (tid < s) {
            sf[tid] += sf[tid + s];
            si[tid] += si[tid + s];
            sc[tid] += sc[tid + s];
        }
        __syncthreads();
    }
    if (tid == 0) {
        d_sumyp[c] = sf[0];
        d_npos[c]  = si[0];
        d_cap[c]   = sc[0];
    }
}

__global__ void loss_kernel(const float* __restrict__ epoch_pred,
                            const float* __restrict__ epoch_true,
                            const float* __restrict__ rand_pos,
                            const float* __restrict__ rand_neg,
                            const float* __restrict__ gamma,
                            int Bn, int Cn, int En, int chunks)
{
    int c   = blockIdx.y;
    int tid = threadIdx.x;
    int j   = blockIdx.x * TPB + tid;

    float g   = gamma[c];
    float cap = fmaxf((float)d_cap[c], 1.0f);
    float p   = 1000.0f / cap;

    bool selpos = false, selneg = false;
    float tval = 0.f;
    if (j < En) {
        int off = j * Cn + c;
        float e  = epoch_pred[off];
        bool etb = epoch_true[off] >= 0.5f;
        if (etb) {
            selpos = rand_pos[off] < p;   // epoch positive, subsampled
            tval = g - e;                 // relu(tval + y_i) for batch negs
        } else {
            selneg = rand_neg[off] < p;   // epoch negative, subsampled
            tval = e + g;                 // relu(tval - y_i) for batch pos
        }
    }

    __shared__ float s_tn[TPB];   // t-values of selected epoch negatives
    __shared__ float s_tp[TPB];   // t-values of selected epoch positives
    __shared__ int wcN[8], wcP[8];

    unsigned bn = __ballot_sync(0xffffffffu, selneg);
    unsigned bp = __ballot_sync(0xffffffffu, selpos);
    int lane = tid & 31, w = tid >> 5;
    if (lane == 0) { wcN[w] = __popc(bn); wcP[w] = __popc(bp); }
    __syncthreads();
    int offN = 0, offP = 0, totN = 0, totP = 0;
    #pragma unroll
    for (int k = 0; k < 8; k++) {
        int vn = wcN[k], vp = wcP[k];
        if (k < w) { offN += vn; offP += vp; }
        totN += vn; totP += vp;
    }
    unsigned lmask = (1u << lane) - 1u;
    if (selneg) s_tn[offN + __popc(bn & lmask)] = tval;
    if (selpos) s_tp[offP + __popc(bp & lmask)] = tval;
    __syncthreads();

    // Thread tid owns batch element tid for this class.
    float apos = d_Apos[c * TPB + tid];   // y (pos) or 1e30
    float aneg = d_Aneg[c * TPB + tid];   // -y (neg) or 1e30
    float acc = 0.f;

    // m2: selected epoch negatives vs batch positives
    #pragma unroll 4
    for (int k = 0; k < totN; k++) {
        float d = s_tn[k] - apos;         // e + g - y
        float r = fmaxf(d, 0.f);
        acc = fmaf(r, r, acc);
    }
    // m3: selected epoch positives vs batch negatives
    #pragma unroll 4
    for (int k = 0; k < totP; k++) {
        float d = s_tp[k] - aneg;         // (g - e) - (-y) = y - e + g
        float r = fmaxf(d, 0.f);
        acc = fmaf(r, r, acc);
    }

    __shared__ float red[TPB];
    red[tid] = acc;
    __syncthreads();
    for (int s = TPB / 2; s > 0; s >>= 1) {
        if (tid < s) red[tid] += red[tid + s];
        __syncthreads();
    }
    if (tid == 0) d_part[c * chunks + blockIdx.x] = red[0];
}

__global__ void finalize_kernel(float* __restrict__ out, int Bn, int Cn, int chunks)
{
    int c = threadIdx.x;
    float res = 0.f;
    if (c < Cn) {
        float m = 0.f;
        for (int k = 0; k < chunks; k++) m += d_part[c * chunks + k];
        res = m / 1000.0f;                 // m2/MAX_POS + m3/MAX_NEG
        if (isnan(res)) res = 0.f;
        int np = d_npos[c];
        if (np == 0 || np == Bn) res = d_sumyp[c] * 1e-8f;  // degenerate
    }
    #pragma unroll
    for (int o = 16; o > 0; o >>= 1)
        res += __shfl_down_sync(0xffffffffu, res, o);
    if (c == 0) out[0] = res / (float)Cn;
}

extern "C" void kernel_launch(void* const* d_in, const int* in_sizes, int n_in,
                              void* d_out, int out_size)
{
    const float* y_pred     = (const float*)d_in[0];
    const float* y_true     = (const float*)d_in[1];
    const float* epoch_pred = (const float*)d_in[2];
    const float* epoch_true = (const float*)d_in[3];
    const float* gamma      = (const float*)d_in[4];
    const float* rand_pos   = (const float*)d_in[5];
    const float* rand_neg   = (const float*)d_in[6];

    int Cn = in_sizes[4];            // gamma has C elements
    int Bn = in_sizes[0] / Cn;       // y_pred is [B, C]
    int En = in_sizes[2] / Cn;       // epoch_pred is [E, C]
    int chunks = (En + TPB - 1) / TPB;

    setup_kernel<<<Cn, TPB>>>(y_pred, y_true, epoch_true, Bn, Cn, En);
    dim3 grid(chunks, Cn);
    loss_kernel<<<grid, TPB>>>(epoch_pred, epoch_true, rand_pos, rand_neg,
                               gamma, Bn, Cn, En, chunks);
    finalize_kernel<<<1, 32>>>((float*)d_out, Bn, Cn, chunks);
}